// round 10
// baseline (speedup 1.0000x reference)
#include <cuda_runtime.h>
#include <math.h>

#define N_GRAPHS   200000
#define NODES_PG   37
#define N_NODES    (N_GRAPHS * NODES_PG)      // 7,400,000
#define N_EDGES    (8 * N_NODES)              // 59,200,000

// Scratch: per-node aggregation buffer (atomic scatter target). 29.6 MB.
__device__ float g_agg[N_NODES];

// ---------------------------------------------------------------------------
// Kernel 1: init accumulator with x*root + conv_bias (float4).
// ---------------------------------------------------------------------------
__global__ void __launch_bounds__(256) init_kernel(
    const float* __restrict__ x,
    const float* __restrict__ root,
    const float* __restrict__ conv_bias)
{
    const float r  = __ldg(root);
    const float cb = __ldg(conv_bias);
    int i = blockIdx.x * blockDim.x + threadIdx.x;          // float4 index
    if (i < N_NODES / 4) {
        float4 xv = __ldg((const float4*)x + i);
        float4 o;
        o.x = fmaf(xv.x, r, cb);
        o.y = fmaf(xv.y, r, cb);
        o.z = fmaf(xv.z, r, cb);
        o.w = fmaf(xv.w, r, cb);
        ((float4*)g_agg)[i] = o;
    }
}

// ---------------------------------------------------------------------------
// Kernel 2: per-edge message + scatter-add (4 edges/thread, measured-best).
// R10 change: x gathers use __ldcg (L2-only) — L1 hit rate on the 29.6MB x
// array is <1%, so L1 line allocation is pure overhead on a pipe at 84%.
//   ew = relu(ea*W1 + b1) @ W2 + b2 ;  agg[dst] += x[src] * ew  (RED.ADD)
// ---------------------------------------------------------------------------
__global__ void __launch_bounds__(256) edge_kernel(
    const float* __restrict__ x,
    const float* __restrict__ ea,
    const int*   __restrict__ src,
    const int*   __restrict__ dst,
    const float* __restrict__ W1, const float* __restrict__ b1,
    const float* __restrict__ W2, const float* __restrict__ b2,
    int e0, int count)
{
    const float w10 = __ldg(W1 + 0), w11 = __ldg(W1 + 1),
                w12 = __ldg(W1 + 2), w13 = __ldg(W1 + 3);
    const float c10 = __ldg(b1 + 0), c11 = __ldg(b1 + 1),
                c12 = __ldg(b1 + 2), c13 = __ldg(b1 + 3);
    const float w20 = __ldg(W2 + 0), w21 = __ldg(W2 + 1),
                w22 = __ldg(W2 + 2), w23 = __ldg(W2 + 3);
    const float c20 = __ldg(b2 + 0);

    int t = blockIdx.x * blockDim.x + threadIdx.x;
    int base = t * 4;
    if (base >= count) return;
    base += e0;

    float4 a = *(const float4*)(ea  + base);
    int4   s = *(const int4*)  (src + base);
    int4   d = *(const int4*)  (dst + base);

    // per-edge 1->4->1 MLP
    #define EW(av) (c20 \
        + fmaxf(fmaf((av), w10, c10), 0.f) * w20 \
        + fmaxf(fmaf((av), w11, c11), 0.f) * w21 \
        + fmaxf(fmaf((av), w12, c12), 0.f) * w22 \
        + fmaxf(fmaf((av), w13, c13), 0.f) * w23)

    float e0w = EW(a.x), e1w = EW(a.y), e2w = EW(a.z), e3w = EW(a.w);
    #undef EW

    float x0 = __ldcg(x + s.x);
    float x1 = __ldcg(x + s.y);
    float x2 = __ldcg(x + s.z);
    float x3 = __ldcg(x + s.w);

    atomicAdd(&g_agg[d.x], x0 * e0w);
    atomicAdd(&g_agg[d.y], x1 * e1w);
    atomicAdd(&g_agg[d.z], x2 * e2w);
    atomicAdd(&g_agg[d.w], x3 * e3w);
}

// ---------------------------------------------------------------------------
// Kernel 3: per-graph MLP + angle. agg already holds nodes (init folded).
//   g(37) -> relu(37x8) -> relu(8x8) -> (8x2) -> angle
// ---------------------------------------------------------------------------
#define GPB 128   // graphs per block

__global__ void __launch_bounds__(GPB) mlp_kernel(
    const float* __restrict__ Wa, const float* __restrict__ ba,
    const float* __restrict__ Wb, const float* __restrict__ bb,
    const float* __restrict__ Wc, const float* __restrict__ bc,
    float* __restrict__ out)
{
    __shared__ float sn[GPB * NODES_PG];      // 4736 floats
    __shared__ float sWa[NODES_PG * 8];       // 296 floats
    __shared__ float sba[8];
    __shared__ float sWb[64];
    __shared__ float sbb[8];
    __shared__ float sWc[16];
    __shared__ float sbc[2];

    const int tid = threadIdx.x;
    const int g0  = blockIdx.x * GPB;

    for (int j = tid; j < NODES_PG * 8; j += GPB) sWa[j] = Wa[j];
    if (tid < 8)  sba[tid] = ba[tid];
    if (tid < 64) sWb[tid] = Wb[tid];
    if (tid >= 64 && tid < 72) sbb[tid - 64] = bb[tid - 64];
    if (tid >= 72 && tid < 88) sWc[tid - 72] = Wc[tid - 72];
    if (tid >= 88 && tid < 90) sbc[tid - 88] = bc[tid - 88];

    int ngr = N_GRAPHS - g0;
    if (ngr > GPB) ngr = GPB;
    const int limit = ngr * NODES_PG;
    const int gbase = g0 * NODES_PG;

    for (int j = tid; j < limit; j += GPB) {
        sn[j] = g_agg[gbase + j];
    }
    __syncthreads();

    const int g = g0 + tid;
    if (g >= N_GRAPHS) return;

    const float* nv = &sn[tid * NODES_PG];

    float h1[8];
    #pragma unroll
    for (int k = 0; k < 8; k++) h1[k] = sba[k];
    #pragma unroll
    for (int i = 0; i < NODES_PG; i++) {
        float v = nv[i];
        #pragma unroll
        for (int k = 0; k < 8; k++) h1[k] = fmaf(v, sWa[i * 8 + k], h1[k]);
    }
    #pragma unroll
    for (int k = 0; k < 8; k++) h1[k] = fmaxf(h1[k], 0.f);

    float h2[8];
    #pragma unroll
    for (int k = 0; k < 8; k++) h2[k] = sbb[k];
    #pragma unroll
    for (int j = 0; j < 8; j++) {
        float v = h1[j];
        #pragma unroll
        for (int k = 0; k < 8; k++) h2[k] = fmaf(v, sWb[j * 8 + k], h2[k]);
    }
    #pragma unroll
    for (int k = 0; k < 8; k++) h2[k] = fmaxf(h2[k], 0.f);

    float X = sbc[0], Y = sbc[1];
    #pragma unroll
    for (int j = 0; j < 8; j++) {
        X = fmaf(h2[j], sWc[j * 2 + 0], X);
        Y = fmaf(h2[j], sWc[j * 2 + 1], Y);
    }

    const float PI  = 3.14159265358979323846f;
    float sgnY = (Y > 0.f) ? 1.f : ((Y < 0.f) ? -1.f : 0.f);
    float angle = atanf(X / Y) + 0.5f * PI * sgnY + PI;
    out[g] = angle * (12.0f / (2.0f * PI));
}

// ---------------------------------------------------------------------------
// Launch
// ---------------------------------------------------------------------------
extern "C" void kernel_launch(void* const* d_in, const int* in_sizes, int n_in,
                              void* d_out, int out_size) {
    const float* x    = (const float*)d_in[0];
    const float* ea   = (const float*)d_in[1];
    const float* W1   = (const float*)d_in[2];
    const float* b1   = (const float*)d_in[3];
    const float* W2   = (const float*)d_in[4];
    const float* b2   = (const float*)d_in[5];
    const float* root = (const float*)d_in[6];
    const float* cbi  = (const float*)d_in[7];
    const float* Wa   = (const float*)d_in[8];
    const float* ba   = (const float*)d_in[9];
    const float* Wb   = (const float*)d_in[10];
    const float* bb   = (const float*)d_in[11];
    const float* Wc   = (const float*)d_in[12];
    const float* bc   = (const float*)d_in[13];
    const int*   eidx = (const int*)d_in[14];
    float* out = (float*)d_out;

    const int* src = eidx;            // edge_index row 0
    const int* dst = eidx + N_EDGES;  // edge_index row 1

    // 1) init accumulator with x*root + conv_bias (also warms L2 with x)
    {
        int n4 = N_NODES / 4;
        int blocks = (n4 + 255) / 256;
        init_kernel<<<blocks, 256>>>(x, root, cbi);
    }
    // 2) edge scatter, split into three launches (profiling alignment:
    //    2 prefix launches + s=5 -> slot 3 of this 5-launch call = edge_c).
    //    Atomics make the parts order-independent.
    {
        const int P1 = 19733336;                 // divisible by 4
        const int P2 = 19733332;                 // divisible by 4
        const int P3 = N_EDGES - P1 - P2;        // 19733332, divisible by 4
        int blocks1 = (P1 / 4 + 255) / 256;
        int blocks2 = (P2 / 4 + 255) / 256;
        int blocks3 = (P3 / 4 + 255) / 256;
        edge_kernel<<<blocks1, 256>>>(x, ea, src, dst, W1, b1, W2, b2, 0,       P1);
        edge_kernel<<<blocks2, 256>>>(x, ea, src, dst, W1, b1, W2, b2, P1,      P2);
        edge_kernel<<<blocks3, 256>>>(x, ea, src, dst, W1, b1, W2, b2, P1 + P2, P3);
    }
    // 3) per-graph MLP + angle
    {
        int blocks = (N_GRAPHS + GPB - 1) / GPB;
        mlp_kernel<<<blocks, GPB>>>(Wa, ba, Wb, bb, Wc, bc, out);
    }
}

// round 11
// speedup vs baseline: 1.0171x; 1.0171x over previous
#include <cuda_runtime.h>
#include <math.h>

#define N_GRAPHS   200000
#define NODES_PG   37
#define N_NODES    (N_GRAPHS * NODES_PG)      // 7,400,000
#define N_EDGES    (8 * N_NODES)              // 59,200,000

// Scratch: per-node aggregation buffer (atomic scatter target). 29.6 MB.
__device__ float g_agg[N_NODES];

// ---------------------------------------------------------------------------
// Kernel 1: init accumulator with x*root + conv_bias (float4).
// ---------------------------------------------------------------------------
__global__ void __launch_bounds__(256) init_kernel(
    const float* __restrict__ x,
    const float* __restrict__ root,
    const float* __restrict__ conv_bias)
{
    const float r  = __ldg(root);
    const float cb = __ldg(conv_bias);
    int i = blockIdx.x * blockDim.x + threadIdx.x;          // float4 index
    if (i < N_NODES / 4) {
        float4 xv = __ldg((const float4*)x + i);
        float4 o;
        o.x = fmaf(xv.x, r, cb);
        o.y = fmaf(xv.y, r, cb);
        o.z = fmaf(xv.z, r, cb);
        o.w = fmaf(xv.w, r, cb);
        ((float4*)g_agg)[i] = o;
    }
}

// ---------------------------------------------------------------------------
// Kernel 2: per-edge message + scatter-add (4 edges/thread, block=512 probe).
// Processes edges [e0, e0+count).
//   ew = relu(ea*W1 + b1) @ W2 + b2 ;  agg[dst] += x[src] * ew  (RED.ADD)
// ---------------------------------------------------------------------------
#define EBLK 512

__global__ void __launch_bounds__(EBLK) edge_kernel(
    const float* __restrict__ x,
    const float* __restrict__ ea,
    const int*   __restrict__ src,
    const int*   __restrict__ dst,
    const float* __restrict__ W1, const float* __restrict__ b1,
    const float* __restrict__ W2, const float* __restrict__ b2,
    int e0, int count)
{
    const float w10 = __ldg(W1 + 0), w11 = __ldg(W1 + 1),
                w12 = __ldg(W1 + 2), w13 = __ldg(W1 + 3);
    const float c10 = __ldg(b1 + 0), c11 = __ldg(b1 + 1),
                c12 = __ldg(b1 + 2), c13 = __ldg(b1 + 3);
    const float w20 = __ldg(W2 + 0), w21 = __ldg(W2 + 1),
                w22 = __ldg(W2 + 2), w23 = __ldg(W2 + 3);
    const float c20 = __ldg(b2 + 0);

    int t = blockIdx.x * blockDim.x + threadIdx.x;
    int base = t * 4;
    if (base >= count) return;
    base += e0;

    float4 a = *(const float4*)(ea  + base);
    int4   s = *(const int4*)  (src + base);
    int4   d = *(const int4*)  (dst + base);

    // per-edge 1->4->1 MLP
    #define EW(av) (c20 \
        + fmaxf(fmaf((av), w10, c10), 0.f) * w20 \
        + fmaxf(fmaf((av), w11, c11), 0.f) * w21 \
        + fmaxf(fmaf((av), w12, c12), 0.f) * w22 \
        + fmaxf(fmaf((av), w13, c13), 0.f) * w23)

    float e0w = EW(a.x), e1w = EW(a.y), e2w = EW(a.z), e3w = EW(a.w);
    #undef EW

    float x0 = __ldg(x + s.x);
    float x1 = __ldg(x + s.y);
    float x2 = __ldg(x + s.z);
    float x3 = __ldg(x + s.w);

    atomicAdd(&g_agg[d.x], x0 * e0w);
    atomicAdd(&g_agg[d.y], x1 * e1w);
    atomicAdd(&g_agg[d.z], x2 * e2w);
    atomicAdd(&g_agg[d.w], x3 * e3w);
}

// ---------------------------------------------------------------------------
// Kernel 3: per-graph MLP + angle. agg already holds nodes (init folded).
//   g(37) -> relu(37x8) -> relu(8x8) -> (8x2) -> angle
// ---------------------------------------------------------------------------
#define GPB 128   // graphs per block

__global__ void __launch_bounds__(GPB) mlp_kernel(
    const float* __restrict__ Wa, const float* __restrict__ ba,
    const float* __restrict__ Wb, const float* __restrict__ bb,
    const float* __restrict__ Wc, const float* __restrict__ bc,
    float* __restrict__ out)
{
    __shared__ float sn[GPB * NODES_PG];      // 4736 floats
    __shared__ float sWa[NODES_PG * 8];       // 296 floats
    __shared__ float sba[8];
    __shared__ float sWb[64];
    __shared__ float sbb[8];
    __shared__ float sWc[16];
    __shared__ float sbc[2];

    const int tid = threadIdx.x;
    const int g0  = blockIdx.x * GPB;

    for (int j = tid; j < NODES_PG * 8; j += GPB) sWa[j] = Wa[j];
    if (tid < 8)  sba[tid] = ba[tid];
    if (tid < 64) sWb[tid] = Wb[tid];
    if (tid >= 64 && tid < 72) sbb[tid - 64] = bb[tid - 64];
    if (tid >= 72 && tid < 88) sWc[tid - 72] = Wc[tid - 72];
    if (tid >= 88 && tid < 90) sbc[tid - 88] = bc[tid - 88];

    int ngr = N_GRAPHS - g0;
    if (ngr > GPB) ngr = GPB;
    const int limit = ngr * NODES_PG;
    const int gbase = g0 * NODES_PG;

    for (int j = tid; j < limit; j += GPB) {
        sn[j] = g_agg[gbase + j];
    }
    __syncthreads();

    const int g = g0 + tid;
    if (g >= N_GRAPHS) return;

    const float* nv = &sn[tid * NODES_PG];

    float h1[8];
    #pragma unroll
    for (int k = 0; k < 8; k++) h1[k] = sba[k];
    #pragma unroll
    for (int i = 0; i < NODES_PG; i++) {
        float v = nv[i];
        #pragma unroll
        for (int k = 0; k < 8; k++) h1[k] = fmaf(v, sWa[i * 8 + k], h1[k]);
    }
    #pragma unroll
    for (int k = 0; k < 8; k++) h1[k] = fmaxf(h1[k], 0.f);

    float h2[8];
    #pragma unroll
    for (int k = 0; k < 8; k++) h2[k] = sbb[k];
    #pragma unroll
    for (int j = 0; j < 8; j++) {
        float v = h1[j];
        #pragma unroll
        for (int k = 0; k < 8; k++) h2[k] = fmaf(v, sWb[j * 8 + k], h2[k]);
    }
    #pragma unroll
    for (int k = 0; k < 8; k++) h2[k] = fmaxf(h2[k], 0.f);

    float X = sbc[0], Y = sbc[1];
    #pragma unroll
    for (int j = 0; j < 8; j++) {
        X = fmaf(h2[j], sWc[j * 2 + 0], X);
        Y = fmaf(h2[j], sWc[j * 2 + 1], Y);
    }

    const float PI  = 3.14159265358979323846f;
    float sgnY = (Y > 0.f) ? 1.f : ((Y < 0.f) ? -1.f : 0.f);
    float angle = atanf(X / Y) + 0.5f * PI * sgnY + PI;
    out[g] = angle * (12.0f / (2.0f * PI));
}

// ---------------------------------------------------------------------------
// Launch
// ---------------------------------------------------------------------------
extern "C" void kernel_launch(void* const* d_in, const int* in_sizes, int n_in,
                              void* d_out, int out_size) {
    const float* x    = (const float*)d_in[0];
    const float* ea   = (const float*)d_in[1];
    const float* W1   = (const float*)d_in[2];
    const float* b1   = (const float*)d_in[3];
    const float* W2   = (const float*)d_in[4];
    const float* b2   = (const float*)d_in[5];
    const float* root = (const float*)d_in[6];
    const float* cbi  = (const float*)d_in[7];
    const float* Wa   = (const float*)d_in[8];
    const float* ba   = (const float*)d_in[9];
    const float* Wb   = (const float*)d_in[10];
    const float* bb   = (const float*)d_in[11];
    const float* Wc   = (const float*)d_in[12];
    const float* bc   = (const float*)d_in[13];
    const int*   eidx = (const int*)d_in[14];
    float* out = (float*)d_out;

    const int* src = eidx;            // edge_index row 0
    const int* dst = eidx + N_EDGES;  // edge_index row 1

    // 1) init accumulator with x*root + conv_bias (also warms L2 with x)
    {
        int n4 = N_NODES / 4;
        int blocks = (n4 + 255) / 256;
        init_kernel<<<blocks, 256>>>(x, root, cbi);
    }
    // 2) edge scatter, split into two half-range launches (best measured;
    //    atomics make the halves order-independent)
    {
        const int HALF = N_EDGES / 2;            // divisible by 4
        int nthreads = HALF / 4;
        int blocks = (nthreads + EBLK - 1) / EBLK;
        edge_kernel<<<blocks, EBLK>>>(x, ea, src, dst, W1, b1, W2, b2, 0,    HALF);
        edge_kernel<<<blocks, EBLK>>>(x, ea, src, dst, W1, b1, W2, b2, HALF, HALF);
    }
    // 3) per-graph MLP + angle
    {
        int blocks = (N_GRAPHS + GPB - 1) / GPB;
        mlp_kernel<<<blocks, GPB>>>(Wa, ba, Wb, bb, Wc, bc, out);
    }
}

// round 12
// speedup vs baseline: 1.0213x; 1.0041x over previous
#include <cuda_runtime.h>
#include <math.h>

#define N_GRAPHS   200000
#define NODES_PG   37
#define N_NODES    (N_GRAPHS * NODES_PG)      // 7,400,000
#define N_EDGES    (8 * N_NODES)              // 59,200,000

// Scratch: per-node aggregation buffer (atomic scatter target). 29.6 MB.
__device__ float g_agg[N_NODES];

// ---------------------------------------------------------------------------
// Kernel 1: init accumulator with x*root + conv_bias (float4).
// ---------------------------------------------------------------------------
__global__ void __launch_bounds__(256) init_kernel(
    const float* __restrict__ x,
    const float* __restrict__ root,
    const float* __restrict__ conv_bias)
{
    const float r  = __ldg(root);
    const float cb = __ldg(conv_bias);
    int i = blockIdx.x * blockDim.x + threadIdx.x;          // float4 index
    if (i < N_NODES / 4) {
        float4 xv = __ldg((const float4*)x + i);
        float4 o;
        o.x = fmaf(xv.x, r, cb);
        o.y = fmaf(xv.y, r, cb);
        o.z = fmaf(xv.z, r, cb);
        o.w = fmaf(xv.w, r, cb);
        ((float4*)g_agg)[i] = o;
    }
}

// ---------------------------------------------------------------------------
// Kernel 2: per-edge message + scatter-add. EPT=2 probe (trend: smaller EPT
// has been monotonically better: 4:458 < 8:468 < 16:482).
// Processes edges [e0, e0+count).
//   ew = relu(ea*W1 + b1) @ W2 + b2 ;  agg[dst] += x[src] * ew  (RED.ADD)
// ---------------------------------------------------------------------------
__global__ void __launch_bounds__(256) edge_kernel(
    const float* __restrict__ x,
    const float* __restrict__ ea,
    const int*   __restrict__ src,
    const int*   __restrict__ dst,
    const float* __restrict__ W1, const float* __restrict__ b1,
    const float* __restrict__ W2, const float* __restrict__ b2,
    int e0, int count)
{
    const float w10 = __ldg(W1 + 0), w11 = __ldg(W1 + 1),
                w12 = __ldg(W1 + 2), w13 = __ldg(W1 + 3);
    const float c10 = __ldg(b1 + 0), c11 = __ldg(b1 + 1),
                c12 = __ldg(b1 + 2), c13 = __ldg(b1 + 3);
    const float w20 = __ldg(W2 + 0), w21 = __ldg(W2 + 1),
                w22 = __ldg(W2 + 2), w23 = __ldg(W2 + 3);
    const float c20 = __ldg(b2 + 0);

    int t = blockIdx.x * blockDim.x + threadIdx.x;
    int base = t * 2;
    if (base >= count) return;
    base += e0;

    float2 a = *(const float2*)(ea  + base);
    int2   s = *(const int2*)  (src + base);
    int2   d = *(const int2*)  (dst + base);

    // per-edge 1->4->1 MLP
    #define EW(av) (c20 \
        + fmaxf(fmaf((av), w10, c10), 0.f) * w20 \
        + fmaxf(fmaf((av), w11, c11), 0.f) * w21 \
        + fmaxf(fmaf((av), w12, c12), 0.f) * w22 \
        + fmaxf(fmaf((av), w13, c13), 0.f) * w23)

    float e0w = EW(a.x), e1w = EW(a.y);
    #undef EW

    float x0 = __ldg(x + s.x);
    float x1 = __ldg(x + s.y);

    atomicAdd(&g_agg[d.x], x0 * e0w);
    atomicAdd(&g_agg[d.y], x1 * e1w);
}

// ---------------------------------------------------------------------------
// Kernel 3: per-graph MLP + angle. agg already holds nodes (init folded).
//   g(37) -> relu(37x8) -> relu(8x8) -> (8x2) -> angle
// ---------------------------------------------------------------------------
#define GPB 128   // graphs per block

__global__ void __launch_bounds__(GPB) mlp_kernel(
    const float* __restrict__ Wa, const float* __restrict__ ba,
    const float* __restrict__ Wb, const float* __restrict__ bb,
    const float* __restrict__ Wc, const float* __restrict__ bc,
    float* __restrict__ out)
{
    __shared__ float sn[GPB * NODES_PG];      // 4736 floats
    __shared__ float sWa[NODES_PG * 8];       // 296 floats
    __shared__ float sba[8];
    __shared__ float sWb[64];
    __shared__ float sbb[8];
    __shared__ float sWc[16];
    __shared__ float sbc[2];

    const int tid = threadIdx.x;
    const int g0  = blockIdx.x * GPB;

    for (int j = tid; j < NODES_PG * 8; j += GPB) sWa[j] = Wa[j];
    if (tid < 8)  sba[tid] = ba[tid];
    if (tid < 64) sWb[tid] = Wb[tid];
    if (tid >= 64 && tid < 72) sbb[tid - 64] = bb[tid - 64];
    if (tid >= 72 && tid < 88) sWc[tid - 72] = Wc[tid - 72];
    if (tid >= 88 && tid < 90) sbc[tid - 88] = bc[tid - 88];

    int ngr = N_GRAPHS - g0;
    if (ngr > GPB) ngr = GPB;
    const int limit = ngr * NODES_PG;
    const int gbase = g0 * NODES_PG;

    for (int j = tid; j < limit; j += GPB) {
        sn[j] = g_agg[gbase + j];
    }
    __syncthreads();

    const int g = g0 + tid;
    if (g >= N_GRAPHS) return;

    const float* nv = &sn[tid * NODES_PG];

    float h1[8];
    #pragma unroll
    for (int k = 0; k < 8; k++) h1[k] = sba[k];
    #pragma unroll
    for (int i = 0; i < NODES_PG; i++) {
        float v = nv[i];
        #pragma unroll
        for (int k = 0; k < 8; k++) h1[k] = fmaf(v, sWa[i * 8 + k], h1[k]);
    }
    #pragma unroll
    for (int k = 0; k < 8; k++) h1[k] = fmaxf(h1[k], 0.f);

    float h2[8];
    #pragma unroll
    for (int k = 0; k < 8; k++) h2[k] = sbb[k];
    #pragma unroll
    for (int j = 0; j < 8; j++) {
        float v = h1[j];
        #pragma unroll
        for (int k = 0; k < 8; k++) h2[k] = fmaf(v, sWb[j * 8 + k], h2[k]);
    }
    #pragma unroll
    for (int k = 0; k < 8; k++) h2[k] = fmaxf(h2[k], 0.f);

    float X = sbc[0], Y = sbc[1];
    #pragma unroll
    for (int j = 0; j < 8; j++) {
        X = fmaf(h2[j], sWc[j * 2 + 0], X);
        Y = fmaf(h2[j], sWc[j * 2 + 1], Y);
    }

    const float PI  = 3.14159265358979323846f;
    float sgnY = (Y > 0.f) ? 1.f : ((Y < 0.f) ? -1.f : 0.f);
    float angle = atanf(X / Y) + 0.5f * PI * sgnY + PI;
    out[g] = angle * (12.0f / (2.0f * PI));
}

// ---------------------------------------------------------------------------
// Launch
// ---------------------------------------------------------------------------
extern "C" void kernel_launch(void* const* d_in, const int* in_sizes, int n_in,
                              void* d_out, int out_size) {
    const float* x    = (const float*)d_in[0];
    const float* ea   = (const float*)d_in[1];
    const float* W1   = (const float*)d_in[2];
    const float* b1   = (const float*)d_in[3];
    const float* W2   = (const float*)d_in[4];
    const float* b2   = (const float*)d_in[5];
    const float* root = (const float*)d_in[6];
    const float* cbi  = (const float*)d_in[7];
    const float* Wa   = (const float*)d_in[8];
    const float* ba   = (const float*)d_in[9];
    const float* Wb   = (const float*)d_in[10];
    const float* bb   = (const float*)d_in[11];
    const float* Wc   = (const float*)d_in[12];
    const float* bc   = (const float*)d_in[13];
    const int*   eidx = (const int*)d_in[14];
    float* out = (float*)d_out;

    const int* src = eidx;            // edge_index row 0
    const int* dst = eidx + N_EDGES;  // edge_index row 1

    // 1) init accumulator with x*root + conv_bias (also warms L2 with x)
    {
        int n4 = N_NODES / 4;
        int blocks = (n4 + 255) / 256;
        init_kernel<<<blocks, 256>>>(x, root, cbi);
    }
    // 2) edge scatter, split into two half-range launches (atomics make the
    //    halves order-independent)
    {
        const int HALF = N_EDGES / 2;            // divisible by 2
        int nthreads = HALF / 2;
        int blocks = (nthreads + 255) / 256;
        edge_kernel<<<blocks, 256>>>(x, ea, src, dst, W1, b1, W2, b2, 0,    HALF);
        edge_kernel<<<blocks, 256>>>(x, ea, src, dst, W1, b1, W2, b2, HALF, HALF);
    }
    // 3) per-graph MLP + angle
    {
        int blocks = (N_GRAPHS + GPB - 1) / GPB;
        mlp_kernel<<<blocks, GPB>>>(Wa, ba, Wb, bb, Wc, bc, out);
    }
}